// round 1
// baseline (speedup 1.0000x reference)
#include <cuda_runtime.h>
#include <math.h>

// NTM memory addressing + read/write.
// Inputs (metadata order): memory(B,N,M) prev_w(B,N) k(B,M) beta(B,1) g(B,1) s(3) y(B,1) e(B,M) a(B,M)
// Output buffer layout: read(B,M) | mem_new(B,N,M) | w(B,N)
// B=8192, N=128, M=64

#define BB 8192
#define NN 128
#define MM 64
#define STR 65   // padded row stride: bank = (n*65+m) % 32 = (n+m)%32 -> conflict-free column reads

__device__ __forceinline__ float blk_max128(float v, volatile float* red) {
    #pragma unroll
    for (int o = 16; o; o >>= 1) v = fmaxf(v, __shfl_xor_sync(0xffffffffu, v, o));
    if ((threadIdx.x & 31) == 0) red[threadIdx.x >> 5] = v;
    __syncthreads();
    v = fmaxf(fmaxf(red[0], red[1]), fmaxf(red[2], red[3]));
    __syncthreads();
    return v;
}

__device__ __forceinline__ float blk_sum128(float v, volatile float* red) {
    #pragma unroll
    for (int o = 16; o; o >>= 1) v += __shfl_xor_sync(0xffffffffu, v, o);
    if ((threadIdx.x & 31) == 0) red[threadIdx.x >> 5] = v;
    __syncthreads();
    v = (red[0] + red[1]) + (red[2] + red[3]);
    __syncthreads();
    return v;
}

__global__ __launch_bounds__(128) void ntm_kernel(
    const float* __restrict__ memory,
    const float* __restrict__ prev_w,
    const float* __restrict__ k,
    const float* __restrict__ beta,
    const float* __restrict__ g,
    const float* __restrict__ s,
    const float* __restrict__ y,
    const float* __restrict__ e,
    const float* __restrict__ a,
    float* __restrict__ out_read,
    float* __restrict__ out_mem,
    float* __restrict__ out_w)
{
    __shared__ float sm[NN * STR];     // memory tile, padded
    __shared__ float sk[MM], se[MM], sa[MM];
    __shared__ float sw[NN + 2];       // wg with circular halo
    __shared__ float swf[NN];          // final w
    __shared__ float rbuf[128];        // read partials
    __shared__ float red[4];           // reduction scratch

    const int b   = blockIdx.x;
    const int tid = threadIdx.x;

    const float* memb = memory + (size_t)b * (NN * MM);

    if (tid < MM) {
        sk[tid] = k[b * MM + tid];
        se[tid] = e[b * MM + tid];
        sa[tid] = a[b * MM + tid];
    }

    // coalesced load of 128x64 tile into padded smem
    #pragma unroll 8
    for (int i = 0; i < 64; i++) {
        int idx = i * 128 + tid;
        sm[(idx >> 6) * STR + (idx & 63)] = memb[idx];
    }
    __syncthreads();

    // --- content addressing: thread n owns row n ---
    float ksq = 0.f;
    #pragma unroll
    for (int m = 0; m < MM; m++) { float kk = sk[m]; ksq += kk * kk; }

    float dot = 0.f, msq = 0.f;
    const float* row = &sm[tid * STR];
    #pragma unroll
    for (int m = 0; m < MM; m++) {
        float v = row[m];
        dot += v * sk[m];
        msq += v * v;
    }
    float knorm = fmaxf(sqrtf(ksq), 1e-8f);
    float mnorm = fmaxf(sqrtf(msq), 1e-8f);
    float logit = beta[b] * (dot / (knorm * mnorm));

    // softmax across 128 rows
    float mx = blk_max128(logit, red);
    float ex = expf(logit - mx);
    float sden = blk_sum128(ex, red);
    float wc = ex / sden;

    // gate interpolation
    float gb = g[b];
    float wg = gb * wc + (1.f - gb) * prev_w[b * NN + tid];
    sw[tid + 1] = wg;
    __syncthreads();
    if (tid == 0) { sw[0] = sw[NN]; sw[NN + 1] = sw[1]; }
    __syncthreads();

    // circular shift + sharpen
    float s0 = s[0], s1 = s[1], s2 = s[2];
    float wt = s0 * sw[tid] + s1 * sw[tid + 1] + s2 * sw[tid + 2];
    float wp = powf(wt, y[b]);
    float psum = blk_sum128(wp, red);
    float wfin = wp / psum;
    swf[tid] = wfin;
    out_w[b * NN + tid] = wfin;
    __syncthreads();

    // --- read: read[m] = sum_n w[n]*mem[n,m]; split n-range over two halves ---
    {
        int m = tid & 63;
        int h = tid >> 6;              // 0 or 1
        float r = 0.f;
        int n0 = h * 64;
        #pragma unroll
        for (int n = 0; n < 64; n++) {
            int nn = n0 + n;
            r += swf[nn] * sm[nn * STR + m];
        }
        rbuf[tid] = r;
    }
    __syncthreads();
    if (tid < MM) out_read[b * MM + tid] = rbuf[tid] + rbuf[tid + 64];

    // --- erase/add write, coalesced ---
    float* omem = out_mem + (size_t)b * (NN * MM);
    #pragma unroll 8
    for (int i = 0; i < 64; i++) {
        int idx = i * 128 + tid;
        int n = idx >> 6, m = idx & 63;
        float v  = sm[n * STR + m];
        float wn = swf[n];
        omem[idx] = v * (1.f - wn * se[m]) + wn * sa[m];
    }
}

extern "C" void kernel_launch(void* const* d_in, const int* in_sizes, int n_in,
                              void* d_out, int out_size)
{
    const float* memory = (const float*)d_in[0];
    const float* prev_w = (const float*)d_in[1];
    const float* k      = (const float*)d_in[2];
    const float* beta   = (const float*)d_in[3];
    const float* g      = (const float*)d_in[4];
    const float* s      = (const float*)d_in[5];
    const float* y      = (const float*)d_in[6];
    const float* e      = (const float*)d_in[7];
    const float* a      = (const float*)d_in[8];

    float* out = (float*)d_out;
    float* out_read = out;
    float* out_mem  = out + (size_t)BB * MM;
    float* out_w    = out + (size_t)BB * MM + (size_t)BB * NN * MM;

    ntm_kernel<<<BB, 128>>>(memory, prev_w, k, beta, g, s, y, e, a,
                            out_read, out_mem, out_w);
}

// round 2
// speedup vs baseline: 1.0769x; 1.0769x over previous
#include <cuda_runtime.h>
#include <math.h>

// NTM memory addressing + read/write.
// Inputs: memory(B,N,M) prev_w(B,N) k(B,M) beta(B,1) g(B,1) s(3) y(B,1) e(B,M) a(B,M)
// Output layout: read(B,M) | mem_new(B,N,M) | w(B,N)
// B=8192, N=128, M=64

#define BB 8192
#define NN 128
#define MM 64

__global__ __launch_bounds__(256, 6) void ntm_kernel(
    const float* __restrict__ memory,
    const float* __restrict__ prev_w,
    const float* __restrict__ k,
    const float* __restrict__ beta,
    const float* __restrict__ g,
    const float* __restrict__ s,
    const float* __restrict__ y,
    const float* __restrict__ e,
    const float* __restrict__ a,
    float* __restrict__ out_read,
    float* __restrict__ out_mem,
    float* __restrict__ out_w)
{
    // XOR-swizzled tile: element (n,m) at sm[n*64 + (m ^ (n&31))].
    // Row reads (fixed warp step m, n = lane): bank = m^(n&31) -> bijection, conflict-free.
    // Fixed-n warp reads (m = lane span): bank = m^(n&31) -> bijection, conflict-free.
    __shared__ float sm[NN * MM];      // 32 KB
    __shared__ float sk[MM], se[MM], sa[MM];
    __shared__ float sw[NN + 2];       // wg with circular halo
    __shared__ float swf[NN];          // final w
    __shared__ float rbuf[256];        // read partials
    __shared__ float red[4];           // reduction scratch

    const int b = blockIdx.x;
    const int t = threadIdx.x;

    const float* memb = memory + (size_t)b * (NN * MM);

    if (t < MM) {
        sk[t] = k[b * MM + t];
        se[t] = e[b * MM + t];
        sa[t] = a[b * MM + t];
    }

    // coalesced load, swizzled store (32 iters x 256 threads)
    #pragma unroll 8
    for (int i = 0; i < 32; i++) {
        int idx = i * 256 + t;
        int n = idx >> 6, m = idx & 63;
        sm[n * 64 + (m ^ (n & 31))] = memb[idx];
    }
    __syncthreads();

    // --- content addressing: threads 0..127 own one row each ---
    float logit = 0.f;
    if (t < NN) {
        float ksq = 0.f;
        #pragma unroll
        for (int m = 0; m < MM; m++) { float kk = sk[m]; ksq += kk * kk; }

        float dot = 0.f, msq = 0.f;
        const int base = t * 64;
        const int x = t & 31;
        #pragma unroll
        for (int m = 0; m < MM; m++) {
            float v = sm[base + (m ^ x)];
            dot += v * sk[m];
            msq += v * v;
        }
        float knorm = fmaxf(sqrtf(ksq), 1e-8f);
        float mnorm = fmaxf(sqrtf(msq), 1e-8f);
        logit = beta[b] * (dot / (knorm * mnorm));
    }

    // softmax over 128 rows (warps 0-3 hold values)
    if (t < NN) {
        float v = logit;
        #pragma unroll
        for (int o = 16; o; o >>= 1) v = fmaxf(v, __shfl_xor_sync(0xffffffffu, v, o));
        if ((t & 31) == 0) red[t >> 5] = v;
    }
    __syncthreads();
    float mx = fmaxf(fmaxf(red[0], red[1]), fmaxf(red[2], red[3]));
    __syncthreads();

    float ex = 0.f;
    if (t < NN) {
        ex = expf(logit - mx);
        float v = ex;
        #pragma unroll
        for (int o = 16; o; o >>= 1) v += __shfl_xor_sync(0xffffffffu, v, o);
        if ((t & 31) == 0) red[t >> 5] = v;
    }
    __syncthreads();
    float sden = (red[0] + red[1]) + (red[2] + red[3]);
    __syncthreads();

    if (t < NN) {
        float wc = ex / sden;
        float gb = g[b];
        float wg = gb * wc + (1.f - gb) * prev_w[b * NN + t];
        sw[t + 1] = wg;
    }
    __syncthreads();
    if (t == 0) { sw[0] = sw[NN]; sw[NN + 1] = sw[1]; }
    __syncthreads();

    // circular shift + sharpen
    float wp = 0.f;
    if (t < NN) {
        float wt = s[0] * sw[t] + s[1] * sw[t + 1] + s[2] * sw[t + 2];
        wp = powf(wt, y[b]);
        float v = wp;
        #pragma unroll
        for (int o = 16; o; o >>= 1) v += __shfl_xor_sync(0xffffffffu, v, o);
        if ((t & 31) == 0) red[t >> 5] = v;
    }
    __syncthreads();
    float psum = (red[0] + red[1]) + (red[2] + red[3]);
    if (t < NN) {
        float wfin = wp / psum;
        swf[t] = wfin;
        out_w[b * NN + t] = wfin;
    }
    __syncthreads();

    // --- read: read[m] = sum_n w[n]*mem[n,m]; 4 groups of 64 threads ---
    {
        const int m = t & 63;
        const int grp = t >> 6;        // 0..3
        float r = 0.f;
        #pragma unroll
        for (int i = 0; i < 32; i++) {
            int n = grp + 4 * i;
            r += swf[n] * sm[n * 64 + (m ^ (n & 31))];
        }
        rbuf[t] = r;
    }
    __syncthreads();
    if (t < MM)
        out_read[b * MM + t] = (rbuf[t] + rbuf[t + 64]) + (rbuf[t + 128] + rbuf[t + 192]);

    // --- erase/add write, coalesced ---
    float* omem = out_mem + (size_t)b * (NN * MM);
    #pragma unroll 8
    for (int i = 0; i < 32; i++) {
        int idx = i * 256 + t;
        int n = idx >> 6, m = idx & 63;
        float v  = sm[n * 64 + (m ^ (n & 31))];
        float wn = swf[n];
        omem[idx] = v * (1.f - wn * se[m]) + wn * sa[m];
    }
}

extern "C" void kernel_launch(void* const* d_in, const int* in_sizes, int n_in,
                              void* d_out, int out_size)
{
    const float* memory = (const float*)d_in[0];
    const float* prev_w = (const float*)d_in[1];
    const float* k      = (const float*)d_in[2];
    const float* beta   = (const float*)d_in[3];
    const float* g      = (const float*)d_in[4];
    const float* s      = (const float*)d_in[5];
    const float* y      = (const float*)d_in[6];
    const float* e      = (const float*)d_in[7];
    const float* a      = (const float*)d_in[8];

    float* out = (float*)d_out;
    float* out_read = out;
    float* out_mem  = out + (size_t)BB * MM;
    float* out_w    = out + (size_t)BB * MM + (size_t)BB * NN * MM;

    ntm_kernel<<<BB, 256>>>(memory, prev_w, k, beta, g, s, y, e, a,
                            out_read, out_mem, out_w);
}

// round 3
// speedup vs baseline: 1.1229x; 1.0427x over previous
#include <cuda_runtime.h>
#include <math.h>

// NTM memory addressing + read/write. Fully float4-vectorized global + smem traffic.
// Inputs: memory(B,N,M) prev_w(B,N) k(B,M) beta(B,1) g(B,1) s(3) y(B,1) e(B,M) a(B,M)
// Output layout: read(B,M) | mem_new(B,N,M) | w(B,N);  B=8192, N=128, M=64

#define BB 8192
#define NN 128
#define MM 64

__global__ __launch_bounds__(256, 6) void ntm_kernel(
    const float4* __restrict__ memory,
    const float*  __restrict__ prev_w,
    const float4* __restrict__ k,
    const float*  __restrict__ beta,
    const float*  __restrict__ g,
    const float*  __restrict__ s,
    const float*  __restrict__ y,
    const float4* __restrict__ e,
    const float4* __restrict__ a,
    float* __restrict__ out_read,
    float4* __restrict__ out_mem,
    float* __restrict__ out_w)
{
    // Tile as float4: element quad (n, g) at sm4[n*16 + (g ^ (n&15))].
    __shared__ float4 sm4[NN * 16];    // 32 KB
    __shared__ float4 sk4[16], se4[16], sa4[16];
    __shared__ float sw[NN + 2];       // wg with circular halo
    __shared__ float swf[NN];          // final w
    __shared__ float rbuf[256];        // read partials
    __shared__ float red[4];           // reduction scratch

    const int b = blockIdx.x;
    const int t = threadIdx.x;

    const float4* memb = memory + (size_t)b * (NN * 16);

    if (t < 16)      sk4[t]      = k[b * 16 + t];
    else if (t < 32) se4[t - 16] = e[b * 16 + (t - 16)];
    else if (t < 48) sa4[t - 32] = a[b * 16 + (t - 32)];

    // vectorized coalesced load, swizzled store: 2048 float4, 8 iters x 256 thr
    #pragma unroll 8
    for (int i = 0; i < 8; i++) {
        int idx = i * 256 + t;
        int n = idx >> 4, gg = idx & 15;
        sm4[n * 16 + (gg ^ (n & 15))] = __ldcs(&memb[idx]);
    }
    __syncthreads();

    // --- content addressing: threads 0..127 own one row each ---
    float logit = 0.f;
    if (t < NN) {
        float ksq = 0.f;
        #pragma unroll
        for (int gq = 0; gq < 16; gq++) {
            float4 kk = sk4[gq];
            ksq += kk.x * kk.x + kk.y * kk.y + kk.z * kk.z + kk.w * kk.w;
        }
        float dot = 0.f, msq = 0.f;
        const int base = t * 16;
        const int x = t & 15;
        #pragma unroll
        for (int gq = 0; gq < 16; gq++) {
            float4 v  = sm4[base + (gq ^ x)];
            float4 kk = sk4[gq];
            dot += v.x * kk.x + v.y * kk.y + v.z * kk.z + v.w * kk.w;
            msq += v.x * v.x  + v.y * v.y  + v.z * v.z  + v.w * v.w;
        }
        float knorm = fmaxf(sqrtf(ksq), 1e-8f);
        float mnorm = fmaxf(sqrtf(msq), 1e-8f);
        logit = beta[b] * (dot / (knorm * mnorm));
    }

    // softmax over 128 rows
    if (t < NN) {
        float v = logit;
        #pragma unroll
        for (int o = 16; o; o >>= 1) v = fmaxf(v, __shfl_xor_sync(0xffffffffu, v, o));
        if ((t & 31) == 0) red[t >> 5] = v;
    }
    __syncthreads();
    float mx = fmaxf(fmaxf(red[0], red[1]), fmaxf(red[2], red[3]));
    __syncthreads();

    float ex = 0.f;
    if (t < NN) {
        ex = expf(logit - mx);
        float v = ex;
        #pragma unroll
        for (int o = 16; o; o >>= 1) v += __shfl_xor_sync(0xffffffffu, v, o);
        if ((t & 31) == 0) red[t >> 5] = v;
    }
    __syncthreads();
    float sden = (red[0] + red[1]) + (red[2] + red[3]);
    __syncthreads();

    if (t < NN) {
        float wc = ex / sden;
        float gb = g[b];
        float wg = gb * wc + (1.f - gb) * prev_w[b * NN + t];
        sw[t + 1] = wg;
    }
    __syncthreads();
    if (t == 0) { sw[0] = sw[NN]; sw[NN + 1] = sw[1]; }
    __syncthreads();

    // circular shift + sharpen
    float wp = 0.f;
    if (t < NN) {
        float wt = s[0] * sw[t] + s[1] * sw[t + 1] + s[2] * sw[t + 2];
        wp = powf(wt, y[b]);
        float v = wp;
        #pragma unroll
        for (int o = 16; o; o >>= 1) v += __shfl_xor_sync(0xffffffffu, v, o);
        if ((t & 31) == 0) red[t >> 5] = v;
    }
    __syncthreads();
    float psum = (red[0] + red[1]) + (red[2] + red[3]);
    if (t < NN) {
        float wfin = wp / psum;
        swf[t] = wfin;
        out_w[b * NN + t] = wfin;
    }
    __syncthreads();

    const float* smf = (const float*)sm4;

    // --- read: read[m] = sum_n w[n]*mem[n,m]; 4 groups of 64 threads ---
    {
        const int m = t & 63;
        const int grp = t >> 6;        // 0..3
        const int mq = m >> 2, ml = m & 3;
        float r = 0.f;
        #pragma unroll
        for (int i = 0; i < 32; i++) {
            int n = grp + 4 * i;
            r += swf[n] * smf[(n * 16 + (mq ^ (n & 15))) * 4 + ml];
        }
        rbuf[t] = r;
    }
    __syncthreads();
    if (t < MM)
        out_read[b * MM + t] = (rbuf[t] + rbuf[t + 64]) + (rbuf[t + 128] + rbuf[t + 192]);

    // --- erase/add write: vectorized, coalesced ---
    float4* omem = out_mem + (size_t)b * (NN * 16);
    #pragma unroll 8
    for (int i = 0; i < 8; i++) {
        int idx = i * 256 + t;
        int n = idx >> 4, gg = idx & 15;
        float4 v  = sm4[n * 16 + (gg ^ (n & 15))];
        float wn  = swf[n];
        float4 ev = se4[gg], av = sa4[gg];
        float4 o;
        o.x = v.x * (1.f - wn * ev.x) + wn * av.x;
        o.y = v.y * (1.f - wn * ev.y) + wn * av.y;
        o.z = v.z * (1.f - wn * ev.z) + wn * av.z;
        o.w = v.w * (1.f - wn * ev.w) + wn * av.w;
        __stcs(&omem[idx], o);
    }
}

extern "C" void kernel_launch(void* const* d_in, const int* in_sizes, int n_in,
                              void* d_out, int out_size)
{
    const float4* memory = (const float4*)d_in[0];
    const float*  prev_w = (const float*)d_in[1];
    const float4* k      = (const float4*)d_in[2];
    const float*  beta   = (const float*)d_in[3];
    const float*  g      = (const float*)d_in[4];
    const float*  s      = (const float*)d_in[5];
    const float*  y      = (const float*)d_in[6];
    const float4* e      = (const float4*)d_in[7];
    const float4* a      = (const float4*)d_in[8];

    float* out = (float*)d_out;
    float*  out_read = out;
    float4* out_mem  = (float4*)(out + (size_t)BB * MM);
    float*  out_w    = out + (size_t)BB * MM + (size_t)BB * NN * MM;

    ntm_kernel<<<BB, 256>>>(memory, prev_w, k, beta, g, s, y, e, a,
                            out_read, out_mem, out_w);
}

// round 4
// speedup vs baseline: 1.2228x; 1.0889x over previous
#include <cuda_runtime.h>
#include <math.h>

// NTM memory addressing + read/write. Register-resident tile, no smem round-trip.
// Inputs: memory(B,N,M) prev_w(B,N) k(B,M) beta(B,1) g(B,1) s(3) y(B,1) e(B,M) a(B,M)
// Output layout: read(B,M) | mem_new(B,N,M) | w(B,N);  B=8192, N=128, M=64

#define BB 8192
#define NN 128
#define MM 64

__device__ __forceinline__ float red16(float v) {
    v += __shfl_xor_sync(0xffffffffu, v, 8);
    v += __shfl_xor_sync(0xffffffffu, v, 4);
    v += __shfl_xor_sync(0xffffffffu, v, 2);
    v += __shfl_xor_sync(0xffffffffu, v, 1);
    return v;
}

__global__ __launch_bounds__(256, 4) void ntm_kernel(
    const float4* __restrict__ memory,
    const float*  __restrict__ prev_w,
    const float4* __restrict__ k,
    const float*  __restrict__ beta,
    const float*  __restrict__ g,
    const float*  __restrict__ s,
    const float*  __restrict__ y,
    const float4* __restrict__ e,
    const float4* __restrict__ a,
    float* __restrict__ out_read,
    float4* __restrict__ out_mem,
    float* __restrict__ out_w)
{
    __shared__ float4 sk4[16], se4[16], sa4[16];
    __shared__ float  smLogit[NN];
    __shared__ float  sw[NN + 2];
    __shared__ float  swf[NN];
    __shared__ float  red[4];
    __shared__ float4 rbuf4[256];      // 4 KB read partials

    const int b  = blockIdx.x;
    const int t  = threadIdx.x;
    const int gg = t & 15;             // quad-column owned by this thread
    const int j  = t >> 4;             // row-phase: rows n = 16*i + j

    const float4* memb = memory + (size_t)b * 2048;

    if (t < 16)      sk4[t]      = k[b * 16 + t];
    else if (t < 32) se4[t - 16] = e[b * 16 + (t - 16)];
    else if (t < 48) sa4[t - 32] = a[b * 16 + (t - 32)];
    __syncthreads();

    const float4 kq = sk4[gg];
    const float  ksq   = red16(kq.x*kq.x + kq.y*kq.y + kq.z*kq.z + kq.w*kq.w);
    const float  knorm = fmaxf(sqrtf(ksq), 1e-8f);
    const float  betab = beta[b];

    // --- load full tile into registers (coalesced LDG.128, MLP=8) ---
    float4 v[8];
    #pragma unroll
    for (int i = 0; i < 8; i++)
        v[i] = __ldcs(&memb[i * 256 + t]);

    // --- per-row dot and |m|^2 via 16-lane reductions ---
    #pragma unroll
    for (int i = 0; i < 8; i++) {
        float4 vv = v[i];
        float d  = vv.x*kq.x + vv.y*kq.y + vv.z*kq.z + vv.w*kq.w;
        float ms = vv.x*vv.x + vv.y*vv.y + vv.z*vv.z + vv.w*vv.w;
        d  = red16(d);
        ms = red16(ms);
        if (gg == i) {
            float mnorm = fmaxf(sqrtf(ms), 1e-8f);
            smLogit[16 * i + j] = betab * (d / (knorm * mnorm));
        }
    }
    __syncthreads();

    // --- softmax over 128 rows (threads 0..127) ---
    float logit = 0.f;
    if (t < NN) {
        logit = smLogit[t];
        float vv = logit;
        #pragma unroll
        for (int o = 16; o; o >>= 1) vv = fmaxf(vv, __shfl_xor_sync(0xffffffffu, vv, o));
        if ((t & 31) == 0) red[t >> 5] = vv;
    }
    __syncthreads();
    float mx = fmaxf(fmaxf(red[0], red[1]), fmaxf(red[2], red[3]));
    __syncthreads();

    float ex = 0.f;
    if (t < NN) {
        ex = expf(logit - mx);
        float vv = ex;
        #pragma unroll
        for (int o = 16; o; o >>= 1) vv += __shfl_xor_sync(0xffffffffu, vv, o);
        if ((t & 31) == 0) red[t >> 5] = vv;
    }
    __syncthreads();
    float sden = (red[0] + red[1]) + (red[2] + red[3]);
    __syncthreads();

    if (t < NN) {
        float wc = ex / sden;
        float gb = g[b];
        sw[t + 1] = gb * wc + (1.f - gb) * prev_w[b * NN + t];
    }
    __syncthreads();
    if (t == 0) { sw[0] = sw[NN]; sw[NN + 1] = sw[1]; }
    __syncthreads();

    // --- circular shift + sharpen ---
    float wp = 0.f;
    if (t < NN) {
        float wt = s[0] * sw[t] + s[1] * sw[t + 1] + s[2] * sw[t + 2];
        wp = powf(wt, y[b]);
        float vv = wp;
        #pragma unroll
        for (int o = 16; o; o >>= 1) vv += __shfl_xor_sync(0xffffffffu, vv, o);
        if ((t & 31) == 0) red[t >> 5] = vv;
    }
    __syncthreads();
    float psum = (red[0] + red[1]) + (red[2] + red[3]);
    if (t < NN) {
        float wfin = wp / psum;
        swf[t] = wfin;
        out_w[b * NN + t] = wfin;
    }
    __syncthreads();

    // --- fused erase/add write + read-einsum accumulation ---
    const float4 eq = se4[gg];
    const float4 aq = sa4[gg];
    float4 racc = make_float4(0.f, 0.f, 0.f, 0.f);
    float4* omem = out_mem + (size_t)b * 2048;
    #pragma unroll
    for (int i = 0; i < 8; i++) {
        float wn = swf[16 * i + j];
        float4 vv = v[i], o;
        o.x = vv.x * (1.f - wn * eq.x) + wn * aq.x;
        o.y = vv.y * (1.f - wn * eq.y) + wn * aq.y;
        o.z = vv.z * (1.f - wn * eq.z) + wn * aq.z;
        o.w = vv.w * (1.f - wn * eq.w) + wn * aq.w;
        __stcs(&omem[i * 256 + t], o);
        racc.x += wn * vv.x;
        racc.y += wn * vv.y;
        racc.z += wn * vv.z;
        racc.w += wn * vv.w;
    }
    rbuf4[t] = racc;
    __syncthreads();

    // read[m]: sum partials over the 16 j-phases (thread m < 64, conflict-free)
    if (t < MM) {
        const float* rb = (const float*)rbuf4;
        float r = 0.f;
        #pragma unroll
        for (int jj = 0; jj < 16; jj++)
            r += rb[jj * 64 + t];
        out_read[b * MM + t] = r;
    }
}

extern "C" void kernel_launch(void* const* d_in, const int* in_sizes, int n_in,
                              void* d_out, int out_size)
{
    const float4* memory = (const float4*)d_in[0];
    const float*  prev_w = (const float*)d_in[1];
    const float4* k      = (const float4*)d_in[2];
    const float*  beta   = (const float*)d_in[3];
    const float*  g      = (const float*)d_in[4];
    const float*  s      = (const float*)d_in[5];
    const float*  y      = (const float*)d_in[6];
    const float4* e      = (const float4*)d_in[7];
    const float4* a      = (const float4*)d_in[8];

    float* out = (float*)d_out;
    float*  out_read = out;
    float4* out_mem  = (float4*)(out + (size_t)BB * MM);
    float*  out_w    = out + (size_t)BB * MM + (size_t)BB * NN * MM;

    ntm_kernel<<<BB, 256>>>(memory, prev_w, k, beta, g, s, y, e, a,
                            out_read, out_mem, out_w);
}